// round 16
// baseline (speedup 1.0000x reference)
#include <cuda_runtime.h>
#include <cuda_bf16.h>
#include <cstdint>
#include <math.h>

#define HIDDEN  4096
#define NEXP    128
#define TOPK    8
#define TMAX    16384                // max tokens (4 x 4096)
#define TM      128                  // tokens per CTA
#define KT      64                   // k per stage (64 bf16 = 128B rows)
#define STAGES  (HIDDEN / KT)        // 64
#define THREADS 256                  // 8 warps: 4 (m) x 2 (n)
#define TSTRIDE 144                  // tile row stride bytes (128B data + 16B pad)
#define TILE    (TM * TSTRIDE)       // 18432 B
#define A_OFF(buf,t) ((((buf)*3 + (t))) * TILE)
#define B_OFF(buf,t) ((6 + (buf)*3 + (t)) * TILE)
#define SM_BIAS (12 * TILE)          // 221184
#define SMEM_TOTAL (SM_BIAS + 512)   // 221696 B

// Pre-split operands: 3 bf16 terms each, packed bf16x2 (uint), k-contiguous rows
__device__ unsigned g_B[3][NEXP * HIDDEN / 2];    // weights  [e][k/2]
__device__ unsigned g_A[3][TMAX * HIDDEN / 2];    // hidden   [t][k/2]  (402 MB scratch)

// ---------------- helpers ----------------
__device__ __forceinline__ void cp16(uint32_t dst, const void* src) {
    asm volatile("cp.async.cg.shared.global [%0], [%1], 16;" :: "r"(dst), "l"(src));
}
#define CP_COMMIT() asm volatile("cp.async.commit_group;" ::: "memory")
#define CP_WAIT0()  asm volatile("cp.async.wait_group 0;"  ::: "memory")

__device__ __forceinline__ void ldm4(uint32_t addr, uint32_t* r) {
    asm volatile("ldmatrix.sync.aligned.m8n8.x4.shared.b16 {%0,%1,%2,%3}, [%4];"
                 : "=r"(r[0]), "=r"(r[1]), "=r"(r[2]), "=r"(r[3]) : "r"(addr));
}
__device__ __forceinline__ void mma16816(float* c, const uint32_t* a,
                                         uint32_t b0, uint32_t b1) {
    asm volatile(
        "mma.sync.aligned.m16n8k16.row.col.f32.bf16.bf16.f32 "
        "{%0,%1,%2,%3}, {%4,%5,%6,%7}, {%8,%9}, {%0,%1,%2,%3};"
        : "+f"(c[0]), "+f"(c[1]), "+f"(c[2]), "+f"(c[3])
        : "r"(a[0]), "r"(a[1]), "r"(a[2]), "r"(a[3]), "r"(b0), "r"(b1));
}
// Split fp32 pair into 3 bf16x2 terms (a ~= t1+t2+t3, residual ~2^-27 rel)
__device__ __forceinline__ void split3(float f0, float f1,
                                       unsigned& p1, unsigned& p2, unsigned& p3) {
    asm("cvt.rn.bf16x2.f32 %0, %2, %1;" : "=r"(p1) : "f"(f0), "f"(f1));
    float h0 = __uint_as_float(p1 << 16);
    float h1 = __uint_as_float(p1 & 0xFFFF0000u);
    float r0 = f0 - h0, r1 = f1 - h1;
    asm("cvt.rn.bf16x2.f32 %0, %2, %1;" : "=r"(p2) : "f"(r0), "f"(r1));
    float m0 = __uint_as_float(p2 << 16);
    float m1 = __uint_as_float(p2 & 0xFFFF0000u);
    float s0 = r0 - m0, s1 = r1 - m1;
    asm("cvt.rn.bf16x2.f32 %0, %2, %1;" : "=r"(p3) : "f"(s0), "f"(s1));
}

// ---- once per launch: W -> 3 bf16 term planes ----
__global__ void presplit_w(const float* __restrict__ W) {
    int i = blockIdx.x * 256 + threadIdx.x;              // pair index
    float f0 = W[2 * i], f1 = W[2 * i + 1];
    unsigned p1, p2, p3;
    split3(f0, f1, p1, p2, p3);
    g_B[0][i] = p1; g_B[1][i] = p2; g_B[2][i] = p3;
}

// ---- once per launch: h -> 3 bf16 term planes (same split3 -> bit-exact) ----
__global__ void presplit_h(const float* __restrict__ h) {
    const int idx = blockIdx.x * 256 + threadIdx.x;      // float4 index (2 pairs)
    float4 v = ((const float4*)h)[idx];
    unsigned a1, a2, a3, b1, b2, b3;
    split3(v.x, v.y, a1, a2, a3);
    split3(v.z, v.w, b1, b2, b3);
    ((uint2*)g_A[0])[idx] = make_uint2(a1, b1);
    ((uint2*)g_A[1])[idx] = make_uint2(a2, b2);
    ((uint2*)g_A[2])[idx] = make_uint2(a3, b3);
}

// ---- pipeline building blocks: pure cp.async tile loads ----
__device__ __forceinline__ void issueB(uint32_t sb, int tid, int dstbuf, int k0) {
    #pragma unroll
    for (int j = 0; j < 12; j++) {
        const int c = tid + THREADS * j;
        const int t = c >> 10, row = (c >> 3) & 127, ch = c & 7;
        cp16(sb + B_OFF(dstbuf, t) + row * TSTRIDE + ch * 16,
             (const char*)g_B[t] + (size_t)row * (HIDDEN * 2) + k0 * 2 + ch * 16);
    }
}
__device__ __forceinline__ void issueA(uint32_t sb, int tid, int dstbuf,
                                       int tok0, int k0) {
    #pragma unroll
    for (int j = 0; j < 12; j++) {
        const int c = tid + THREADS * j;
        const int t = c >> 10, row = (c >> 3) & 127, ch = c & 7;
        cp16(sb + A_OFF(dstbuf, t) + row * TSTRIDE + ch * 16,
             (const char*)g_A[t] + (size_t)(tok0 + row) * (HIDDEN * 2) + k0 * 2 + ch * 16);
    }
}

// ---------------- fused GEMM(6-term bf16 HMMA) + sigmoid + top-8 ----------------
__global__ __launch_bounds__(THREADS, 1)
void router_mma_kernel(const float* __restrict__ bias,
                       float* __restrict__ outI,
                       float* __restrict__ outW)
{
    extern __shared__ char smem[];
    const uint32_t sb = (uint32_t)__cvta_generic_to_shared(smem);
    const int tid  = threadIdx.x;
    const int lane = tid & 31;
    const int w    = tid >> 5;
    const int mw   = w >> 1;          // warp m index 0..3 (32 tokens each)
    const int nw   = w & 1;           // warp n index 0..1 (64 experts each)
    const int tok0 = blockIdx.x * TM;

    float* bias_s = (float*)(smem + SM_BIAS);
    if (tid < NEXP) bias_s[tid] = bias[tid];

    float mst[2][8][4];               // master accumulator (RN adds, CUDA cores)
    #pragma unroll
    for (int mt = 0; mt < 2; mt++)
        #pragma unroll
        for (int nt = 0; nt < 8; nt++)
            #pragma unroll
            for (int c = 0; c < 4; c++) mst[mt][nt][c] = 0.f;

    // ---- prologue: A(0)+B(0) into buf0 ----
    issueA(sb, tid, 0, tok0, 0);
    issueB(sb, tid, 0, 0);
    CP_COMMIT();
    CP_WAIT0();
    __syncthreads();

    // products (a_term, b_term): 22,13,31,12,21,11  — ORDER IS LOAD-BEARING
    // (verified-passing R10/R14/R15 numerics; do not reorder p/k16 loops)
    const int ta[6] = {1, 0, 2, 0, 1, 0};
    const int tb[6] = {1, 2, 0, 1, 0, 0};

    for (int s = 0; s < STAGES; s++) {
        const int buf = s & 1;
        const int nb  = buf ^ 1;

        if (s + 1 < STAGES) {         // prefetch (s+1) into nb: pure cp.async
            issueA(sb, tid, nb, tok0, (s + 1) * KT);
            issueB(sb, tid, nb, (s + 1) * KT);
            CP_COMMIT();
        }

        // ---- compute(s): EXACT R10/R15 block (bit-identical accumulation) ----
        float frg[2][8][4];
        #pragma unroll
        for (int mt = 0; mt < 2; mt++)
            #pragma unroll
            for (int nt = 0; nt < 8; nt++)
                #pragma unroll
                for (int c = 0; c < 4; c++) frg[mt][nt][c] = 0.f;

        const uint32_t lrow = (uint32_t)(lane & 15) * TSTRIDE + (uint32_t)(lane >> 4) * 16;
        #pragma unroll
        for (int p = 0; p < 6; p++) {
            const uint32_t aBase = sb + A_OFF(buf, ta[p]) + mw * 32 * TSTRIDE + lrow;
            const uint32_t bBase = sb + B_OFF(buf, tb[p]) + nw * 64 * TSTRIDE + lrow;
            #pragma unroll
            for (int k16 = 0; k16 < 4; k16++) {
                const uint32_t kb = k16 * 32;
                uint32_t af[2][4];
                ldm4(aBase + kb, af[0]);
                ldm4(aBase + kb + 16 * TSTRIDE, af[1]);
                uint32_t bf[8][2];
                #pragma unroll
                for (int g = 0; g < 4; g++) {
                    uint32_t r[4];
                    ldm4(bBase + kb + g * 16 * TSTRIDE, r);
                    bf[2*g][0]   = r[0]; bf[2*g][1]   = r[2];
                    bf[2*g+1][0] = r[1]; bf[2*g+1][1] = r[3];
                }
                #pragma unroll
                for (int mt = 0; mt < 2; mt++)
                    #pragma unroll
                    for (int nt = 0; nt < 8; nt++)
                        mma16816(frg[mt][nt], af[mt], bf[nt][0], bf[nt][1]);
            }
        }
        // flush fragment -> master with round-to-nearest fp32 adds
        #pragma unroll
        for (int mt = 0; mt < 2; mt++)
            #pragma unroll
            for (int nt = 0; nt < 8; nt++)
                #pragma unroll
                for (int c = 0; c < 4; c++) mst[mt][nt][c] += frg[mt][nt][c];

        CP_WAIT0();                   // (s+1) tiles landed
        __syncthreads();              // stage(s) reads done everywhere
    }

    // ---- scores -> smem [128 tokens][132] ----
    float* sc = (float*)smem;
    #pragma unroll
    for (int mt = 0; mt < 2; mt++)
        #pragma unroll
        for (int nt = 0; nt < 8; nt++) {
            const int r = mw * 32 + mt * 16 + (lane >> 2);
            const int c = nw * 64 + nt * 8 + (lane & 3) * 2;
            sc[r * 132 + c]           = mst[mt][nt][0];
            sc[r * 132 + c + 1]       = mst[mt][nt][1];
            sc[(r + 8) * 132 + c]     = mst[mt][nt][2];
            sc[(r + 8) * 132 + c + 1] = mst[mt][nt][3];
        }
    __syncthreads();

    // ---- distributed top-8 (half-warp shuffle, tie -> lowest index) ----
    const unsigned FULL = 0xffffffffu;
    const int tx  = tid & 15;
    const int grp = tid >> 4;                         // 16 groups x 8 tokens
    for (int i = 0; i < 8; i++) {
        const int token = grp * 8 + i;
        float scv[8];
        #pragma unroll
        for (int j = 0; j < 8; j++) {
            float logit = sc[token * 132 + tx * 8 + j];
            float sig = 1.0f / (1.0f + expf(-logit));
            scv[j] = sig + bias_s[tx * 8 + j];        // corrected score
        }
        float rem[8];
        #pragma unroll
        for (int j = 0; j < 8; j++) rem[j] = scv[j];

        int   topi[TOPK]; float topraw[TOPK];
        float denom = 1e-20f;
        #pragma unroll
        for (int sel = 0; sel < TOPK; sel++) {
            float bv = -3.4e38f; int bi = NEXP;
            #pragma unroll
            for (int j = 0; j < 8; j++)
                if (rem[j] > bv) { bv = rem[j]; bi = tx * 8 + j; }
            #pragma unroll
            for (int off = 8; off; off >>= 1) {
                float ov = __shfl_xor_sync(FULL, bv, off, 16);
                int   oi = __shfl_xor_sync(FULL, bi, off, 16);
                if (ov > bv || (ov == bv && oi < bi)) { bv = ov; bi = oi; }
            }
            topi[sel]   = bi;
            float raw   = bv - bias_s[bi];            // raw sigmoid score
            topraw[sel] = raw;
            denom      += raw;
            const int lj = bi - tx * 8;
            if (lj >= 0 && lj < 8) rem[lj] = -3.4e38f;
        }
        if (tx == 0) {
            const size_t t = (size_t)(tok0 + token);
            const float inv = 1.0f / denom;
            #pragma unroll
            for (int sel = 0; sel < TOPK; sel++) {
                outI[t * TOPK + sel] = (float)topi[sel];
                outW[t * TOPK + sel] = topraw[sel] * inv;
            }
        }
    }
}

extern "C" void kernel_launch(void* const* d_in, const int* in_sizes, int n_in,
                              void* d_out, int out_size)
{
    const float* h    = (const float*)d_in[0];
    const float* W    = (const float*)d_in[1];
    const float* bias = (const float*)d_in[2];

    const int T = in_sizes[0] / HIDDEN;               // 16384

    float* out  = (float*)d_out;
    float* outI = out;
    float* outW = out + (size_t)T * TOPK;

    presplit_w<<<NEXP * HIDDEN / 512, 256>>>(W);
    presplit_h<<<(T * (HIDDEN / 4)) / 256, 256>>>(h);

    static int smem_set = 0;
    if (!smem_set) {
        cudaFuncSetAttribute(router_mma_kernel,
                             cudaFuncAttributeMaxDynamicSharedMemorySize, SMEM_TOTAL);
        smem_set = 1;
    }
    router_mma_kernel<<<T / TM, THREADS, SMEM_TOTAL>>>(bias, outI, outW);
}

// round 17
// speedup vs baseline: 1.4595x; 1.4595x over previous
#include <cuda_runtime.h>
#include <cuda_bf16.h>
#include <cstdint>
#include <math.h>

#define HIDDEN  4096
#define NEXP    128
#define TOPK    8
#define TM      64                   // tokens per CTA
#define KT      32                   // k per stage (32 bf16 = 64B rows)
#define STAGES  (HIDDEN / KT)        // 128
#define THREADS 256                  // 8 warps: 4 (m) x 2 (n)
#define TSTRIDE 80                   // row stride bytes (64B data + 16B pad)
#define A_TILE  (TM * TSTRIDE)       // 5120 B
#define B_TILE  (NEXP * TSTRIDE)     // 10240 B
#define A_OFF(buf,t) (((buf)*3 + (t)) * A_TILE)                 // 6 x 5120
#define B_OFF(buf,t) (6*A_TILE + ((buf)*3 + (t)) * B_TILE)      // 6 x 10240
#define SM_BIAS (6*A_TILE + 6*B_TILE)                           // 92160
#define SMEM_TOTAL (SM_BIAS + 512)                              // 92672 B (x2 CTAs = 185344)

// Pre-split router weights: 3 bf16 terms, packed bf16x2, row-major [e][k/2]
__device__ unsigned g_B[3][NEXP * HIDDEN / 2];

// ---------------- helpers ----------------
__device__ __forceinline__ void cp16(uint32_t dst, const void* src) {
    asm volatile("cp.async.cg.shared.global [%0], [%1], 16;" :: "r"(dst), "l"(src));
}
#define CP_COMMIT() asm volatile("cp.async.commit_group;" ::: "memory")
#define CP_WAIT0()  asm volatile("cp.async.wait_group 0;"  ::: "memory")

__device__ __forceinline__ void ldm4(uint32_t addr, uint32_t* r) {
    asm volatile("ldmatrix.sync.aligned.m8n8.x4.shared.b16 {%0,%1,%2,%3}, [%4];"
                 : "=r"(r[0]), "=r"(r[1]), "=r"(r[2]), "=r"(r[3]) : "r"(addr));
}
__device__ __forceinline__ void mma16816(float* c, const uint32_t* a,
                                         uint32_t b0, uint32_t b1) {
    asm volatile(
        "mma.sync.aligned.m16n8k16.row.col.f32.bf16.bf16.f32 "
        "{%0,%1,%2,%3}, {%4,%5,%6,%7}, {%8,%9}, {%0,%1,%2,%3};"
        : "+f"(c[0]), "+f"(c[1]), "+f"(c[2]), "+f"(c[3])
        : "r"(a[0]), "r"(a[1]), "r"(a[2]), "r"(a[3]), "r"(b0), "r"(b1));
}
// Split fp32 pair into 3 bf16x2 terms (a ~= t1+t2+t3, residual ~2^-27 rel)
__device__ __forceinline__ void split3(float f0, float f1,
                                       unsigned& p1, unsigned& p2, unsigned& p3) {
    asm("cvt.rn.bf16x2.f32 %0, %2, %1;" : "=r"(p1) : "f"(f0), "f"(f1));
    float h0 = __uint_as_float(p1 << 16);
    float h1 = __uint_as_float(p1 & 0xFFFF0000u);
    float r0 = f0 - h0, r1 = f1 - h1;
    asm("cvt.rn.bf16x2.f32 %0, %2, %1;" : "=r"(p2) : "f"(r0), "f"(r1));
    float m0 = __uint_as_float(p2 << 16);
    float m1 = __uint_as_float(p2 & 0xFFFF0000u);
    float s0 = r0 - m0, s1 = r1 - m1;
    asm("cvt.rn.bf16x2.f32 %0, %2, %1;" : "=r"(p3) : "f"(s0), "f"(s1));
}

// ---- once per launch: W -> 3 bf16 term planes ----
__global__ void presplit_w(const float* __restrict__ W) {
    int i = blockIdx.x * 256 + threadIdx.x;              // pair index
    float f0 = W[2 * i], f1 = W[2 * i + 1];
    unsigned p1, p2, p3;
    split3(f0, f1, p1, p2, p3);
    g_B[0][i] = p1; g_B[1][i] = p2; g_B[2][i] = p3;
}

// ---- pipeline building blocks ----
__device__ __forceinline__ void issueB(uint32_t sb, int tid, int dstbuf, int k0) {
    // 3 terms x 128 rows x 4 chunks(16B) = 1536 cp16 / 256 thr = 6 each
    #pragma unroll
    for (int j = 0; j < 6; j++) {
        const int c = tid + THREADS * j;
        const int t = c >> 9, row = (c >> 2) & 127, ch = c & 3;
        cp16(sb + B_OFF(dstbuf, t) + row * TSTRIDE + ch * 16,
             (const char*)g_B[t] + (size_t)row * (HIDDEN * 2) + k0 * 2 + ch * 16);
    }
}
// LDG(h) -> split3 -> STS; 64 rows x 8 float4-chunks = 512 / 256 thr = 2 each
__device__ __forceinline__ void fusedA(char* smem, const float* __restrict__ h,
                                       int tid, int tok0, int k0, int dstbuf) {
    #pragma unroll
    for (int j = 0; j < 2; j++) {
        const int c = tid + THREADS * j;
        const int row = c >> 3, ch = c & 7;
        float4 v = *(const float4*)(h + (size_t)(tok0 + row) * HIDDEN + k0 + ch * 4);
        unsigned a1, a2, a3, b1, b2, b3;
        split3(v.x, v.y, a1, a2, a3);
        split3(v.z, v.w, b1, b2, b3);
        const int off = row * TSTRIDE + ch * 8;
        *(uint2*)(smem + A_OFF(dstbuf, 0) + off) = make_uint2(a1, b1);
        *(uint2*)(smem + A_OFF(dstbuf, 1) + off) = make_uint2(a2, b2);
        *(uint2*)(smem + A_OFF(dstbuf, 2) + off) = make_uint2(a3, b3);
    }
}

// ---------------- fused GEMM(6-term bf16 HMMA) + sigmoid + top-8 ----------------
// 2 CTAs/SM. Warp tile: 16 tokens x 64 experts (4 m-warps x 2 n-warps).
__global__ __launch_bounds__(THREADS, 2)
void router_mma_kernel(const float* __restrict__ h,
                       const float* __restrict__ bias,
                       float* __restrict__ outI,
                       float* __restrict__ outW)
{
    extern __shared__ char smem[];
    const uint32_t sb = (uint32_t)__cvta_generic_to_shared(smem);
    const int tid  = threadIdx.x;
    const int lane = tid & 31;
    const int w    = tid >> 5;
    const int mw   = w >> 1;          // warp m index 0..3 (16 tokens each)
    const int nw   = w & 1;           // warp n index 0..1 (64 experts each)
    const int tok0 = blockIdx.x * TM;

    float* bias_s = (float*)(smem + SM_BIAS);
    if (tid < NEXP) bias_s[tid] = bias[tid];

    float mst[8][4];                  // master accumulator (RN adds, CUDA cores)
    #pragma unroll
    for (int nt = 0; nt < 8; nt++)
        #pragma unroll
        for (int c = 0; c < 4; c++) mst[nt][c] = 0.f;

    // ---- prologue ----
    issueB(sb, tid, 0, 0);
    CP_COMMIT();
    fusedA(smem, h, tid, tok0, 0, 0);
    CP_WAIT0();
    __syncthreads();

    // products (a_term, b_term): 22,13,31,12,21,11  — ORDER IS LOAD-BEARING
    const int ta[6] = {1, 0, 2, 0, 1, 0};
    const int tb[6] = {1, 2, 0, 1, 0, 0};

    for (int s = 0; s < STAGES; s++) {
        const int buf = s & 1;
        const int nb  = buf ^ 1;

        if (s + 1 < STAGES) {         // prefetch (s+1) into nb
            issueB(sb, tid, nb, (s + 1) * KT);
            CP_COMMIT();
            fusedA(smem, h, tid, tok0, (s + 1) * KT, nb);
        }

        // ---- compute(s): p-outer, k16-inner (proven order), flush per 32k ----
        float frg[8][4];
        #pragma unroll
        for (int nt = 0; nt < 8; nt++)
            #pragma unroll
            for (int c = 0; c < 4; c++) frg[nt][c] = 0.f;

        const uint32_t lrow = (uint32_t)(lane & 15) * TSTRIDE + (uint32_t)(lane >> 4) * 16;
        #pragma unroll
        for (int p = 0; p < 6; p++) {
            const uint32_t aBase = sb + A_OFF(buf, ta[p]) + mw * 16 * TSTRIDE + lrow;
            const uint32_t bBase = sb + B_OFF(buf, tb[p]) + nw * 64 * TSTRIDE + lrow;
            #pragma unroll
            for (int k16 = 0; k16 < 2; k16++) {
                const uint32_t kb = k16 * 32;
                uint32_t af[4];
                ldm4(aBase + kb, af);
                uint32_t bf[8][2];
                #pragma unroll
                for (int g = 0; g < 4; g++) {
                    uint32_t r[4];
                    ldm4(bBase + kb + g * 16 * TSTRIDE, r);
                    bf[2*g][0]   = r[0]; bf[2*g][1]   = r[2];
                    bf[2*g+1][0] = r[1]; bf[2*g+1][1] = r[3];
                }
                #pragma unroll
                for (int nt = 0; nt < 8; nt++)
                    mma16816(frg[nt], af, bf[nt][0], bf[nt][1]);
            }
        }
        // flush fragment -> master with round-to-nearest fp32 adds
        #pragma unroll
        for (int nt = 0; nt < 8; nt++)
            #pragma unroll
            for (int c = 0; c < 4; c++) mst[nt][c] += frg[nt][c];

        CP_WAIT0();                   // (s+1) tiles landed
        __syncthreads();              // stage(s) reads done everywhere
    }

    // ---- scores -> smem [64 tokens][132] ----
    float* sc = (float*)smem;
    #pragma unroll
    for (int nt = 0; nt < 8; nt++) {
        const int r = mw * 16 + (lane >> 2);
        const int c = nw * 64 + nt * 8 + (lane & 3) * 2;
        sc[r * 132 + c]           = mst[nt][0];
        sc[r * 132 + c + 1]       = mst[nt][1];
        sc[(r + 8) * 132 + c]     = mst[nt][2];
        sc[(r + 8) * 132 + c + 1] = mst[nt][3];
    }
    __syncthreads();

    // ---- distributed top-8 (half-warp shuffle, tie -> lowest index) ----
    const unsigned FULL = 0xffffffffu;
    const int tx  = tid & 15;
    const int grp = tid >> 4;                         // 16 groups x 4 tokens
    for (int i = 0; i < 4; i++) {
        const int token = grp * 4 + i;
        float scv[8];
        #pragma unroll
        for (int j = 0; j < 8; j++) {
            float logit = sc[token * 132 + tx * 8 + j];
            float sig = 1.0f / (1.0f + expf(-logit));
            scv[j] = sig + bias_s[tx * 8 + j];        // corrected score
        }
        float rem[8];
        #pragma unroll
        for (int j = 0; j < 8; j++) rem[j] = scv[j];

        int   topi[TOPK]; float topraw[TOPK];
        float denom = 1e-20f;
        #pragma unroll
        for (int sel = 0; sel < TOPK; sel++) {
            float bv = -3.4e38f; int bi = NEXP;
            #pragma unroll
            for (int j = 0; j < 8; j++)
                if (rem[j] > bv) { bv = rem[j]; bi = tx * 8 + j; }
            #pragma unroll
            for (int off = 8; off; off >>= 1) {
                float ov = __shfl_xor_sync(FULL, bv, off, 16);
                int   oi = __shfl_xor_sync(FULL, bi, off, 16);
                if (ov > bv || (ov == bv && oi < bi)) { bv = ov; bi = oi; }
            }
            topi[sel]   = bi;
            float raw   = bv - bias_s[bi];            // raw sigmoid score
            topraw[sel] = raw;
            denom      += raw;
            const int lj = bi - tx * 8;
            if (lj >= 0 && lj < 8) rem[lj] = -3.4e38f;
        }
        if (tx == 0) {
            const size_t t = (size_t)(tok0 + token);
            const float inv = 1.0f / denom;
            #pragma unroll
            for (int sel = 0; sel < TOPK; sel++) {
                outI[t * TOPK + sel] = (float)topi[sel];
                outW[t * TOPK + sel] = topraw[sel] * inv;
            }
        }
    }
}

extern "C" void kernel_launch(void* const* d_in, const int* in_sizes, int n_in,
                              void* d_out, int out_size)
{
    const float* h    = (const float*)d_in[0];
    const float* W    = (const float*)d_in[1];
    const float* bias = (const float*)d_in[2];

    const int T = in_sizes[0] / HIDDEN;               // 16384

    float* out  = (float*)d_out;
    float* outI = out;
    float* outW = out + (size_t)T * TOPK;

    presplit_w<<<NEXP * HIDDEN / 512, 256>>>(W);

    static int smem_set = 0;
    if (!smem_set) {
        cudaFuncSetAttribute(router_mma_kernel,
                             cudaFuncAttributeMaxDynamicSharedMemorySize, SMEM_TOTAL);
        smem_set = 1;
    }
    router_mma_kernel<<<T / TM, THREADS, SMEM_TOTAL>>>(h, bias, outI, outW);
}